// round 1
// baseline (speedup 1.0000x reference)
#include <cuda_runtime.h>

#define N_NODES 50000
#define N_EDGES 800000
#define FDIM 64

// ---------------- device scratch (static globals: allocation-free) ----------------
__device__ int   g_is64;
__device__ int   g_src[N_EDGES];
__device__ int   g_dst[N_EDGES];
__device__ __align__(16) float g_aggG[N_NODES * FDIM];  // sum dinv[s]dinv[d] * x[s]
__device__ __align__(16) float g_aggA[N_NODES * FDIM];  // sum alpha * x[s]
__device__ __align__(16) float g_aggS[N_NODES * FDIM];  // sum x[s]  (SAGE + GIN shared)
__device__ int   g_cnt[N_NODES];     // in-degree (no self loop)
__device__ float g_denom[N_NODES];   // softmax denominator (incl. self loop)
__device__ float g_ssrc[N_NODES];    // x . (W_gat @ a_src)
__device__ float g_sdst[N_NODES];    // x . (W_gat @ a_dst)
__device__ float g_dinv[N_NODES];    // rsqrt(in-degree + 1)
__device__ float g_va[FDIM];
__device__ float g_vb[FDIM];

__device__ __forceinline__ float lrelu(float v) { return v > 0.f ? v : 0.2f * v; }

__device__ __forceinline__ void red4(float* p, float a, float b, float c, float d) {
    asm volatile("red.global.add.v4.f32 [%0], {%1,%2,%3,%4};"
                 :: "l"(p), "f"(a), "f"(b), "f"(c), "f"(d) : "memory");
}

// ---------------- dtype detection + conversion ----------------
// If edge_index is int64, every odd 32-bit word (high half) of the first 2048
// entries is zero (ids in [0,50000)). If int32, those words are random ids.
__global__ void k_detect(const unsigned int* __restrict__ w) {
    __shared__ int nonzero;
    if (threadIdx.x == 0) nonzero = 0;
    __syncthreads();
    int local = 0;
    for (int i = threadIdx.x; i < 2048; i += blockDim.x)
        if (w[2 * i + 1] != 0u) local = 1;
    if (local) atomicOr(&nonzero, 1);
    __syncthreads();
    if (threadIdx.x == 0) g_is64 = nonzero ? 0 : 1;
}

__global__ void k_convert(const void* __restrict__ ei) {
    int is64 = g_is64;
    int stride = gridDim.x * blockDim.x;
    for (int i = blockIdx.x * blockDim.x + threadIdx.x; i < 2 * N_EDGES; i += stride) {
        int v;
        if (is64) v = (int)((const long long*)ei)[i];
        else      v = ((const int*)ei)[i];
        if (i < N_EDGES) g_src[i] = v;
        else             g_dst[i - N_EDGES] = v;
    }
}

// ---------------- zero accumulators ----------------
__global__ void k_zero() {
    int stride = gridDim.x * blockDim.x;
    int i0 = blockIdx.x * blockDim.x + threadIdx.x;
    float4 z = make_float4(0.f, 0.f, 0.f, 0.f);
    for (int i = i0; i < N_NODES * (FDIM / 4); i += stride) {
        ((float4*)g_aggG)[i] = z;
        ((float4*)g_aggA)[i] = z;
        ((float4*)g_aggS)[i] = z;
    }
    for (int i = i0; i < N_NODES; i += stride) g_cnt[i] = 0;
}

// ---------------- v_a = W_gat @ a_src, v_b = W_gat @ a_dst ----------------
__global__ void k_va(const float* __restrict__ Wa, const float* __restrict__ as_,
                     const float* __restrict__ ad_) {
    int k = threadIdx.x;  // 64 threads
    float va = 0.f, vb = 0.f;
    #pragma unroll 8
    for (int j = 0; j < FDIM; j++) {
        float w = Wa[k * FDIM + j];
        va = fmaf(w, as_[j], va);
        vb = fmaf(w, ad_[j], vb);
    }
    g_va[k] = va;
    g_vb[k] = vb;
}

// ---------------- per-node attention scalars + self-loop exp ----------------
__global__ void k_node1(const float* __restrict__ x) {
    __shared__ float sva[FDIM], svb[FDIM];
    if (threadIdx.x < FDIM) { sva[threadIdx.x] = g_va[threadIdx.x]; svb[threadIdx.x] = g_vb[threadIdx.x]; }
    __syncthreads();
    int n = blockIdx.x * blockDim.x + threadIdx.x;
    if (n >= N_NODES) return;
    const float4* xr = (const float4*)(x + (size_t)n * FDIM);
    float ss = 0.f, sd = 0.f;
    #pragma unroll
    for (int i = 0; i < FDIM / 4; i++) {
        float4 v = xr[i];
        ss = fmaf(v.x, sva[4*i], fmaf(v.y, sva[4*i+1], fmaf(v.z, sva[4*i+2], fmaf(v.w, sva[4*i+3], ss))));
        sd = fmaf(v.x, svb[4*i], fmaf(v.y, svb[4*i+1], fmaf(v.z, svb[4*i+2], fmaf(v.w, svb[4*i+3], sd))));
    }
    g_ssrc[n] = ss;
    g_sdst[n] = sd;
    g_denom[n] = expf(lrelu(ss + sd));   // self-loop term (softmax w/o max shift)
}

// ---------------- per-edge: in-degree count + softmax denominator ----------------
__global__ void k_edge1() {
    int e = blockIdx.x * blockDim.x + threadIdx.x;
    if (e >= N_EDGES) return;
    int s = g_src[e], d = g_dst[e];
    atomicAdd(&g_cnt[d], 1);
    atomicAdd(&g_denom[d], expf(lrelu(g_ssrc[s] + g_sdst[d])));
}

// ---------------- dinv = rsqrt(deg) with self-loop ----------------
__global__ void k_node2() {
    int n = blockIdx.x * blockDim.x + threadIdx.x;
    if (n >= N_NODES) return;
    g_dinv[n] = rsqrtf((float)g_cnt[n] + 1.0f);
}

// ---------------- main edge scatter: 16 threads per edge ----------------
__global__ void k_edge_main(const float* __restrict__ x) {
    long long t = (long long)blockIdx.x * blockDim.x + threadIdx.x;
    int e = (int)(t >> 4);
    if (e >= N_EDGES) return;
    int q = (int)(t & 15);
    int s = g_src[e], d = g_dst[e];
    float wg = g_dinv[s] * g_dinv[d];
    float alpha = expf(lrelu(g_ssrc[s] + g_sdst[d])) / g_denom[d];
    float4 xv = ((const float4*)(x + (size_t)s * FDIM))[q];
    int o = d * FDIM + q * 4;
    red4(&g_aggG[o], xv.x * wg, xv.y * wg, xv.z * wg, xv.w * wg);
    red4(&g_aggA[o], xv.x * alpha, xv.y * alpha, xv.z * alpha, xv.w * alpha);
    red4(&g_aggS[o], xv.x, xv.y, xv.z, xv.w);
}

// ---------------- fused per-node head: 6 matvecs + relu + out head + sigmoid ----------------
#define NB 16
#define RR 4
// smem floats: 5*4096 (weights) + 256 (biases) + 256 (wout) + 5*NB*64 (inputs)
//            + 3*NB (scalars) + 2*NB (reduce) = 26192 floats
#define SMEM_FLOATS (5*4096 + 256 + 256 + 5*NB*64 + 3*NB + 2*NB)
#define SMEM_BYTES (SMEM_FLOATS * 4)

__global__ void k_final(const float* __restrict__ x,
                        const float* __restrict__ Wg, const float* __restrict__ bg,
                        const float* __restrict__ Wa, const float* __restrict__ ba,
                        const float* __restrict__ Wl, const float* __restrict__ bl,
                        const float* __restrict__ Wr,
                        const float* __restrict__ Wi, const float* __restrict__ bi,
                        const float* __restrict__ Wo, const float* __restrict__ bo,
                        float* __restrict__ out) {
    extern __shared__ float sm[];
    float* sW  = sm;                   // [5][64][64]: G, A, sage_l, sage_r, I
    float* sB  = sm + 5 * 4096;        // [4][64]: bG, bA, bS, bI
    float* sWo = sB + 256;             // [4][64]
    float* sIn = sWo + 256;            // [5][NB][64]: a1, a2, mean, gin_in, x
    float* sSc = sIn + 5 * NB * 64;    // [3][NB]: dinv2, alpha_self, cnt_inv
    float* sRd = sSc + 3 * NB;         // [NB][2]
    int tid = threadIdx.x;

    for (int i = tid; i < 4096; i += 256) {
        sW[i]            = Wg[i];
        sW[4096 + i]     = Wa[i];
        sW[2 * 4096 + i] = Wl[i];
        sW[3 * 4096 + i] = Wr[i];
        sW[4 * 4096 + i] = Wi[i];
    }
    if (tid < 64) {
        sB[tid] = bg[tid]; sB[64 + tid] = ba[tid]; sB[128 + tid] = bl[tid]; sB[192 + tid] = bi[tid];
        sWo[tid] = Wo[tid]; sWo[64 + tid] = Wo[64 + tid];
        sWo[128 + tid] = Wo[128 + tid]; sWo[192 + tid] = Wo[192 + tid];
    }
    float bout = bo[0];
    __syncthreads();

    int j = tid & 63;
    int q = tid >> 6;
    float* sA1 = sIn;
    float* sA2 = sIn + NB * 64;
    float* sMn = sIn + 2 * NB * 64;
    float* sGi = sIn + 3 * NB * 64;
    float* sX  = sIn + 4 * NB * 64;

    for (int tile = blockIdx.x; tile < N_NODES / NB; tile += gridDim.x) {
        int base = tile * NB;
        if (tid < NB) {
            int n = base + tid;
            float dv = g_dinv[n];
            sSc[tid] = dv * dv;
            sSc[NB + tid] = expf(lrelu(g_ssrc[n] + g_sdst[n])) / g_denom[n];
            sSc[2 * NB + tid] = 1.0f / fmaxf((float)g_cnt[n], 1.0f);
        }
        __syncthreads();
        {
            int nl = tid >> 4, kq = tid & 15;  // 256 threads == NB*16 float4 slots
            int n = base + nl;
            float4 xv = ((const float4*)x)[n * 16 + kq];
            float4 ag = ((const float4*)g_aggG)[n * 16 + kq];
            float4 aa = ((const float4*)g_aggA)[n * 16 + kq];
            float4 as = ((const float4*)g_aggS)[n * 16 + kq];
            float d2 = sSc[nl], af = sSc[NB + nl], ci = sSc[2 * NB + nl];
            int o = nl * 64 + kq * 4;
            *(float4*)&sA1[o] = make_float4(ag.x + d2 * xv.x, ag.y + d2 * xv.y, ag.z + d2 * xv.z, ag.w + d2 * xv.w);
            *(float4*)&sA2[o] = make_float4(aa.x + af * xv.x, aa.y + af * xv.y, aa.z + af * xv.z, aa.w + af * xv.w);
            *(float4*)&sMn[o] = make_float4(as.x * ci, as.y * ci, as.z * ci, as.w * ci);
            *(float4*)&sGi[o] = make_float4(xv.x + as.x, xv.y + as.y, xv.z + as.z, xv.w + as.w);
            *(float4*)&sX[o]  = xv;
        }
        __syncthreads();

        float accG[RR] = {0.f, 0.f, 0.f, 0.f};
        float accA[RR] = {0.f, 0.f, 0.f, 0.f};
        float accS[RR] = {0.f, 0.f, 0.f, 0.f};
        float accI[RR] = {0.f, 0.f, 0.f, 0.f};
        #pragma unroll 8
        for (int k = 0; k < 64; k++) {
            float wgc = sW[k * 64 + j];
            float wga = sW[4096 + k * 64 + j];
            float wsl = sW[2 * 4096 + k * 64 + j];
            float wsr = sW[3 * 4096 + k * 64 + j];
            float wgi = sW[4 * 4096 + k * 64 + j];
            #pragma unroll
            for (int r = 0; r < RR; r++) {
                int nl = q * RR + r;
                accG[r] = fmaf(sA1[nl * 64 + k], wgc, accG[r]);
                accA[r] = fmaf(sA2[nl * 64 + k], wga, accA[r]);
                accS[r] = fmaf(sMn[nl * 64 + k], wsl, accS[r]);
                accS[r] = fmaf(sX[nl * 64 + k],  wsr, accS[r]);
                accI[r] = fmaf(sGi[nl * 64 + k], wgi, accI[r]);
            }
        }
        #pragma unroll
        for (int r = 0; r < RR; r++) {
            float p = fmaxf(accG[r] + sB[j], 0.f) * sWo[j]
                    + fmaxf(accA[r] + sB[64 + j], 0.f) * sWo[64 + j]
                    + fmaxf(accS[r] + sB[128 + j], 0.f) * sWo[128 + j]
                    + fmaxf(accI[r] + sB[192 + j], 0.f) * sWo[192 + j];
            #pragma unroll
            for (int off = 16; off > 0; off >>= 1)
                p += __shfl_down_sync(0xffffffffu, p, off);
            if ((tid & 31) == 0)
                sRd[(q * RR + r) * 2 + ((j >> 5) & 1)] = p;
        }
        __syncthreads();
        if (tid < NB) {
            float z = sRd[tid * 2] + sRd[tid * 2 + 1] + bout;
            out[base + tid] = 1.0f / (1.0f + expf(-z));
        }
        __syncthreads();
    }
}

// ---------------- launch ----------------
extern "C" void kernel_launch(void* const* d_in, const int* in_sizes, int n_in,
                              void* d_out, int out_size) {
    const float* x    = (const float*)d_in[0];
    const void*  ei   = d_in[1];
    const float* Wg   = (const float*)d_in[2];
    const float* bg   = (const float*)d_in[3];
    const float* Wa   = (const float*)d_in[4];
    const float* asrc = (const float*)d_in[5];
    const float* adst = (const float*)d_in[6];
    const float* ba   = (const float*)d_in[7];
    const float* Wl   = (const float*)d_in[8];
    const float* bl   = (const float*)d_in[9];
    const float* Wr   = (const float*)d_in[10];
    const float* Wi   = (const float*)d_in[11];
    const float* bi   = (const float*)d_in[12];
    const float* Wo   = (const float*)d_in[13];
    const float* bo   = (const float*)d_in[14];
    float* out = (float*)d_out;

    cudaFuncSetAttribute(k_final, cudaFuncAttributeMaxDynamicSharedMemorySize, SMEM_BYTES);

    k_detect<<<1, 256>>>((const unsigned int*)ei);
    k_convert<<<4096, 256>>>(ei);
    k_zero<<<2048, 256>>>();
    k_va<<<1, 64>>>(Wa, asrc, adst);
    k_node1<<<(N_NODES + 255) / 256, 256>>>(x);
    k_edge1<<<(N_EDGES + 255) / 256, 256>>>();
    k_node2<<<(N_NODES + 255) / 256, 256>>>();
    k_edge_main<<<(N_EDGES * 16 + 255) / 256, 256>>>(x);
    k_final<<<296, 256, SMEM_BYTES>>>(x, Wg, bg, Wa, ba, Wl, bl, Wr, Wi, bi, Wo, bo, out);
}